// round 7
// baseline (speedup 1.0000x reference)
#include <cuda_runtime.h>
#include <cuda_bf16.h>
#include <cstdint>

#define H_DIM 4096
#define I_DIM 11008
#define B_DIM 64
#define QGROUP 128

// ---------------------------------------------------------------------------
// Scratch (no device allocation allowed anywhere).
// X/h activations are stored pre-converted to tf32 bits in the exact smem
// tile image: [ktile][64 rows][72 words], pair-permuted within 8-col groups.
// Split-K partials live in L2 (126 MB) between launches -> no DRAM cost.
// ---------------------------------------------------------------------------
__device__ uint32_t g_xt[(H_DIM / 64) * 64 * 72];   // x  as tf32 tiles (1.2 MB)
__device__ uint32_t g_ht[(I_DIM / 64) * 64 * 72];   // h  as tf32 tiles (3.2 MB)
__device__ float g_pg[4 * B_DIM * I_DIM];           // gate split-K partials
__device__ float g_pu[4 * B_DIM * I_DIM];           // up   split-K partials
__device__ float g_pd[4 * B_DIM * H_DIM];           // down split-K partials

#define TILE_WORDS (64 * 72)
#define TILE_BYTES (TILE_WORDS * 4)     // 18432
#define SMEM_BYTES (4 * TILE_BYTES)     // 73728: sX[2] + sW[2]

__device__ __forceinline__ uint32_t f2tf32(float f) {
    uint32_t r;
    asm("cvt.rna.tf32.f32 %0, %1;" : "=r"(r) : "f"(f));
    return r;
}

// permuted position of col c (0..7) within an 8-word k-group: [0,4,1,5,2,6,3,7]
__device__ __forceinline__ int pperm(int c7) { return ((c7 & 3) << 1) | (c7 >> 2); }

__device__ __forceinline__ void mma_tf32(float* c,
                                         uint32_t a0, uint32_t a1, uint32_t a2, uint32_t a3,
                                         uint32_t b0, uint32_t b1) {
    asm volatile(
        "mma.sync.aligned.m16n8k8.row.col.f32.tf32.tf32.f32 "
        "{%0,%1,%2,%3}, {%4,%5,%6,%7}, {%8,%9}, {%0,%1,%2,%3};\n"
        : "+f"(c[0]), "+f"(c[1]), "+f"(c[2]), "+f"(c[3])
        : "r"(a0), "r"(a1), "r"(a2), "r"(a3), "r"(b0), "r"(b1));
}

__device__ __forceinline__ void cp_async16(uint32_t smem_addr, const void* gptr) {
    asm volatile("cp.async.ca.shared.global [%0], [%1], 16;\n"
                 :: "r"(smem_addr), "l"(gptr));
}
__device__ __forceinline__ void cp_commit() {
    asm volatile("cp.async.commit_group;\n");
}
__device__ __forceinline__ void cp_wait0() {
    asm volatile("cp.async.wait_group 0;\n");
}

// ---------------------------------------------------------------------------
// Convert x (f32 row-major [64][H]) -> g_xt tile image (tf32, permuted, padded)
// ---------------------------------------------------------------------------
__global__ void xcvt_kernel(const float* __restrict__ x) {
    const int c = blockIdx.x * 256 + threadIdx.x;   // 0..H-1
    const int m = blockIdx.y;                       // 0..63
    const int tile = c >> 6, cc = c & 63;
    const int ks = cc >> 3, c7 = cc & 7;
    g_xt[(tile * 64 + m) * 72 + ks * 8 + pperm(c7)] = f2tf32(x[m * H_DIM + c]);
}

// ---------------------------------------------------------------------------
// h = silu(gate)*up (reducing 4 split-K partials), emitted as tf32 tile image
// ---------------------------------------------------------------------------
__global__ void silu_kernel() {
    const int c = blockIdx.x * 256 + threadIdx.x;   // 0..I-1
    const int m = blockIdx.y;
    const long idx = (long)m * I_DIM + c;
    const long sl = (long)B_DIM * I_DIM;
    const float gv = (g_pg[idx] + g_pg[sl + idx]) + (g_pg[2 * sl + idx] + g_pg[3 * sl + idx]);
    const float uv = (g_pu[idx] + g_pu[sl + idx]) + (g_pu[2 * sl + idx] + g_pu[3 * sl + idx]);
    const float h = gv * uv / (1.f + __expf(-gv));
    const int tile = c >> 6, cc = c & 63;
    const int ks = cc >> 3, c7 = cc & 7;
    g_ht[(tile * 64 + m) * 72 + ks * 8 + pperm(c7)] = f2tf32(h);
}

// out = sum of 4 down partials
__global__ void add_kernel(float* __restrict__ out) {
    const int i = blockIdx.x * blockDim.x + threadIdx.x;
    out[i] = (g_pd[i] + g_pd[B_DIM * H_DIM + i])
           + (g_pd[2 * B_DIM * H_DIM + i] + g_pd[3 * B_DIM * H_DIM + i]);
}

// ---------------------------------------------------------------------------
// Unified W4A16 GEMM: outp[kz][64, Ntot] = X[64, Kslice] * dequant(Wq)^T
// CTA tile 64x64x64, 4 warps of 32x32. X tiles arrive via cp.async from the
// pre-converted tile image; W dequantized through registers with a 3-instr
// chain (I2F + FFMA(q,s,-z*s) + CVT). Double-buffered, one __syncthreads per
// K iteration. Pair-permuted stride-72 smem rows -> conflict-free LDS.64.
// grid: (Ntot/64, KSPLIT, nmat); blockIdx.z selects weight set (gate/up).
// ---------------------------------------------------------------------------
__global__ __launch_bounds__(128, 3) void gemm_w4(
    const uint32_t* __restrict__ Xt,   // tile image, tile-major
    const int* __restrict__ qA, const float* __restrict__ scA, const float* __restrict__ zrA,
    float* __restrict__ opA,
    const int* __restrict__ qB, const float* __restrict__ scB, const float* __restrict__ zrB,
    float* __restrict__ opB,
    int Kdim, int ksplen, int ng, int Ntot)
{
    const int* q; const float* sc; const float* zr; float* outp;
    if (blockIdx.z == 0) { q = qA; sc = scA; zr = zrA; outp = opA; }
    else                 { q = qB; sc = scB; zr = zrB; outp = opB; }

    extern __shared__ uint32_t smem[];
    uint32_t* sX = smem;                   // [2][64*72]
    uint32_t* sW = smem + 2 * TILE_WORDS;  // [2][64*72]
    const uint32_t sXu = (uint32_t)__cvta_generic_to_shared(sX);

    const int tid  = threadIdx.x;
    const int warp = tid >> 5;
    const int lane = tid & 31;
    const int qg   = lane >> 2;
    const int qt   = lane & 3;
    const int m0w  = (warp & 1) * 32;
    const int n0w  = (warp >> 1) * 32;
    const int n0   = blockIdx.x * 64;
    const int kbeg = blockIdx.y * ksplen;
    const int NT   = ksplen >> 6;
    const int t0   = kbeg >> 6;            // first global k-tile index

    const int ln  = tid >> 2;              // W loader row 0..31 (+32)
    const int lkb = (tid & 3) * 16;        // W loader k-base {0,16,32,48}

    const long wr0 = (long)(n0 + ln) * Kdim;
    const long wr1 = (long)(n0 + ln + 32) * Kdim;

    float acc[2][4][4];
#pragma unroll
    for (int mi = 0; mi < 2; ++mi)
#pragma unroll
        for (int j = 0; j < 4; ++j)
#pragma unroll
            for (int i = 0; i < 4; ++i) acc[mi][j][i] = 0.f;

    int4  wq[8];
    float s0, zs0, s1, zs1;   // zs = -z*s (precomputed per row-tile)

    auto load_w = [&](int k) {
        const int gk = kbeg + k * 64;
        const int gi = gk >> 7;
        s0 = sc[(n0 + ln) * ng + gi];
        zs0 = -zr[(n0 + ln) * ng + gi] * s0;
        s1 = sc[(n0 + ln + 32) * ng + gi];
        zs1 = -zr[(n0 + ln + 32) * ng + gi] * s1;
        const int4* p0 = (const int4*)(q + wr0 + gk + lkb);
        wq[0] = p0[0]; wq[1] = p0[1]; wq[2] = p0[2]; wq[3] = p0[3];
        const int4* p1 = (const int4*)(q + wr1 + gk + lkb);
        wq[4] = p1[0]; wq[5] = p1[1]; wq[6] = p1[2]; wq[7] = p1[3];
    };

    // dequant one element: q*s + (-z*s), single FFMA after I2F
    auto dq1 = [&](int v, float s, float zs) -> uint32_t {
        return f2tf32(fmaf((float)v, s, zs));
    };

    auto put_w = [&](uint32_t* dst, const int4& A, const int4& B, float s, float zs) {
        ((uint4*)dst)[0] = make_uint4(dq1(A.x, s, zs), dq1(B.x, s, zs),
                                      dq1(A.y, s, zs), dq1(B.y, s, zs));
        ((uint4*)dst)[1] = make_uint4(dq1(A.z, s, zs), dq1(B.z, s, zs),
                                      dq1(A.w, s, zs), dq1(B.w, s, zs));
    };

    auto stage_w = [&](int buf) {
        uint32_t* d0 = &sW[buf + ln * 72 + lkb];
        put_w(d0,     wq[0], wq[1], s0, zs0);
        put_w(d0 + 8, wq[2], wq[3], s0, zs0);
        uint32_t* d1 = &sW[buf + (ln + 32) * 72 + lkb];
        put_w(d1,     wq[4], wq[5], s1, zs1);
        put_w(d1 + 8, wq[6], wq[7], s1, zs1);
    };

    // cp.async one X tile image (1152 x 16B chunks) into buffer
    auto fetch_x = [&](int k, int buf_bytes) {
        const char* src = (const char*)(Xt + (long)(t0 + k) * TILE_WORDS);
#pragma unroll
        for (int j = 0; j < 9; ++j) {
            const int off = (j * 128 + tid) * 16;
            cp_async16(sXu + buf_bytes + off, src + off);
        }
        cp_commit();
    };

    // ---- prologue: X(0)+W(0) -> buf0, W(1) -> regs ----
    fetch_x(0, 0);
    load_w(0);
    stage_w(0);
    if (NT > 1) load_w(1);
    cp_wait0();
    __syncthreads();

    for (int k = 0; k < NT; ++k) {
        const int cur = (k & 1) * TILE_WORDS;
        const int nxt = ((k + 1) & 1) * TILE_WORDS;

        if (k + 1 < NT) {
            fetch_x(k + 1, nxt * 4);   // into the buffer retired at last barrier
            stage_w(nxt);              // overlaps this iter's MMA
        }
        if (k + 2 < NT) load_w(k + 2); // LDG 2 iters ahead

#pragma unroll
        for (int ks = 0; ks < 8; ++ks) {
            const int kk = ks * 8 + 2 * qt;
            uint2 aA0 = *(const uint2*)&sX[cur + (m0w + qg)      * 72 + kk];
            uint2 aB0 = *(const uint2*)&sX[cur + (m0w + qg + 8)  * 72 + kk];
            uint2 aA1 = *(const uint2*)&sX[cur + (m0w + qg + 16) * 72 + kk];
            uint2 aB1 = *(const uint2*)&sX[cur + (m0w + qg + 24) * 72 + kk];
#pragma unroll
            for (int j = 0; j < 4; ++j) {
                uint2 bb = *(const uint2*)&sW[cur + (n0w + j * 8 + qg) * 72 + kk];
                mma_tf32(acc[0][j], aA0.x, aB0.x, aA0.y, aB0.y, bb.x, bb.y);
                mma_tf32(acc[1][j], aA1.x, aB1.x, aA1.y, aB1.y, bb.x, bb.y);
            }
        }
        cp_wait0();       // X(k+1) landed (had the whole MMA block to fly)
        __syncthreads();  // publishes X(k+1)+W(k+1); retires reads of cur
    }

    float* ob = outp + (long)blockIdx.y * (B_DIM * (long)Ntot);
#pragma unroll
    for (int mi = 0; mi < 2; ++mi)
#pragma unroll
        for (int j = 0; j < 4; ++j) {
            const int row = m0w + mi * 16 + qg;
            const int col = n0 + n0w + j * 8 + qt * 2;
            *(float2*)&ob[(long)row * Ntot + col] =
                make_float2(acc[mi][j][0], acc[mi][j][1]);
            *(float2*)&ob[(long)(row + 8) * Ntot + col] =
                make_float2(acc[mi][j][2], acc[mi][j][3]);
        }
}

// ---------------------------------------------------------------------------
extern "C" void kernel_launch(void* const* d_in, const int* in_sizes, int n_in,
                              void* d_out, int out_size) {
    (void)in_sizes; (void)n_in; (void)out_size;
    const float* x  = (const float*)d_in[0];
    const int*   gq = (const int*)d_in[1];
    const float* gs = (const float*)d_in[2];
    const float* gz = (const float*)d_in[3];
    const int*   uq = (const int*)d_in[4];
    const float* us = (const float*)d_in[5];
    const float* uz = (const float*)d_in[6];
    const int*   dq = (const int*)d_in[7];
    const float* ds = (const float*)d_in[8];
    const float* dz = (const float*)d_in[9];
    float* out = (float*)d_out;

    // Unconditional (no static guards); idempotent and capture-safe.
    cudaFuncSetAttribute(gemm_w4, cudaFuncAttributeMaxDynamicSharedMemorySize, SMEM_BYTES);

    uint32_t* xt; cudaGetSymbolAddress((void**)&xt, g_xt);
    uint32_t* ht; cudaGetSymbolAddress((void**)&ht, g_ht);
    float* pg; cudaGetSymbolAddress((void**)&pg, g_pg);
    float* pu; cudaGetSymbolAddress((void**)&pu, g_pu);
    float* pd; cudaGetSymbolAddress((void**)&pd, g_pd);

    xcvt_kernel<<<dim3(H_DIM / 256, B_DIM), 256>>>(x);

    // gate + up: grid (172 n-tiles, 4 split-K, 2 matrices) = 1376 CTAs of 16
    // k-iters -> ~3.1 waves at occ 3; work-steal drains the tail (~3-4%).
    gemm_w4<<<dim3(I_DIM / 64, 4, 2), 128, SMEM_BYTES>>>(
        xt, gq, gs, gz, pg, uq, us, uz, pu,
        H_DIM, H_DIM / 4, H_DIM / QGROUP, I_DIM);

    silu_kernel<<<dim3(I_DIM / 256, B_DIM), 256>>>();

    // down: grid (64 n-tiles, 4 split-K) = 256 CTAs of 43 k-iters;
    // per-CTA demand saturates HBM -> rides the DRAM roofline.
    gemm_w4<<<dim3(H_DIM / 64, 4, 1), 128, SMEM_BYTES>>>(
        ht, dq, ds, dz, pd, dq, ds, dz, pd,
        I_DIM, I_DIM / 4, I_DIM / QGROUP, H_DIM);

    add_kernel<<<(B_DIM * H_DIM) / 512, 512>>>(out);
}

// round 12
// speedup vs baseline: 1.0325x; 1.0325x over previous
#include <cuda_runtime.h>
#include <cuda_bf16.h>
#include <cstdint>

#define H_DIM 4096
#define I_DIM 11008
#define B_DIM 64
#define QGROUP 128
#define GU_SPLIT 7
#define DN_SPLIT 6      // base split for down; first DN_NHI tiles get +1
#define DN_NHI   60     // 60*7 + 4*6 = 444 CTAs = exactly one occ-3 wave

// ---------------------------------------------------------------------------
// Scratch (no device allocation allowed anywhere).
// X/h activations pre-converted to tf32 bits in the exact smem tile image:
// [ktile][64 rows][72 words], pair-permuted within 8-col groups.
// ---------------------------------------------------------------------------
__device__ uint32_t g_xt[(H_DIM / 64) * 64 * 72];       // x as tf32 tiles (1.2 MB)
__device__ uint32_t g_ht[(I_DIM / 64) * 64 * 72];       // h as tf32 tiles (3.2 MB)
__device__ float g_pg[GU_SPLIT * B_DIM * I_DIM];        // gate split-K partials
__device__ float g_pu[GU_SPLIT * B_DIM * I_DIM];        // up   split-K partials
__device__ float g_pd[(DN_SPLIT + 1) * B_DIM * H_DIM];  // down split-K partials

#define TILE_WORDS (64 * 72)
#define SMEM_BYTES (4 * TILE_WORDS * 4)   // 73728: sX[2] + sW[2]

__device__ __forceinline__ uint32_t f2tf32(float f) {
    uint32_t r;
    asm("cvt.rna.tf32.f32 %0, %1;" : "=r"(r) : "f"(f));
    return r;
}

// permuted position of col c (0..7) within an 8-word k-group: [0,4,1,5,2,6,3,7]
__device__ __forceinline__ int pperm(int c7) { return ((c7 & 3) << 1) | (c7 >> 2); }

__device__ __forceinline__ void mma_tf32(float* c,
                                         uint32_t a0, uint32_t a1, uint32_t a2, uint32_t a3,
                                         uint32_t b0, uint32_t b1) {
    asm volatile(
        "mma.sync.aligned.m16n8k8.row.col.f32.tf32.tf32.f32 "
        "{%0,%1,%2,%3}, {%4,%5,%6,%7}, {%8,%9}, {%0,%1,%2,%3};\n"
        : "+f"(c[0]), "+f"(c[1]), "+f"(c[2]), "+f"(c[3])
        : "r"(a0), "r"(a1), "r"(a2), "r"(a3), "r"(b0), "r"(b1));
}

__device__ __forceinline__ void cp_async16(uint32_t smem_addr, const void* gptr) {
    asm volatile("cp.async.ca.shared.global [%0], [%1], 16;\n"
                 :: "r"(smem_addr), "l"(gptr));
}
__device__ __forceinline__ void cp_commit() {
    asm volatile("cp.async.commit_group;\n");
}
__device__ __forceinline__ void cp_wait0() {
    asm volatile("cp.async.wait_group 0;\n");
}

// ---------------------------------------------------------------------------
// Convert x (f32 row-major [64][H]) -> g_xt tile image (tf32, permuted, padded)
// ---------------------------------------------------------------------------
__global__ void xcvt_kernel(const float* __restrict__ x) {
    const int c = blockIdx.x * 256 + threadIdx.x;   // 0..H-1
    const int m = blockIdx.y;                       // 0..63
    const int tile = c >> 6, cc = c & 63;
    const int ks = cc >> 3, c7 = cc & 7;
    g_xt[(tile * 64 + m) * 72 + ks * 8 + pperm(c7)] = f2tf32(x[m * H_DIM + c]);
}

// ---------------------------------------------------------------------------
// h = silu(gate)*up (reducing GU_SPLIT partials), emitted as tf32 tile image
// ---------------------------------------------------------------------------
__global__ void silu_kernel() {
    const int c = blockIdx.x * 256 + threadIdx.x;   // 0..I-1
    const int m = blockIdx.y;
    const long idx = (long)m * I_DIM + c;
    const long sl = (long)B_DIM * I_DIM;
    float gv = 0.f, uv = 0.f;
#pragma unroll
    for (int z = 0; z < GU_SPLIT; ++z) {
        gv += g_pg[z * sl + idx];
        uv += g_pu[z * sl + idx];
    }
    const float h = gv * uv / (1.f + __expf(-gv));
    const int tile = c >> 6, cc = c & 63;
    const int ks = cc >> 3, c7 = cc & 7;
    g_ht[(tile * 64 + m) * 72 + ks * 8 + pperm(c7)] = f2tf32(h);
}

// out = sum of down partials; per-column split count (7 for n-tiles < DN_NHI,
// 6 otherwise) so no stale slices are read. H_DIM is a power of two ->
// column extraction is a mask, no integer divide.
__global__ void add_kernel(float* __restrict__ out) {
    const int i = blockIdx.x * blockDim.x + threadIdx.x;
    const int col = i & (H_DIM - 1);
    const int cn = ((col >> 6) < DN_NHI) ? (DN_SPLIT + 1) : DN_SPLIT;
    float v = 0.f;
    for (int z = 0; z < cn; ++z) v += g_pd[z * (B_DIM * H_DIM) + i];
    out[i] = v;
}

// ---------------------------------------------------------------------------
// Unified W4A16 GEMM: outp[s][64, Ntot] = X[64, Kslice] * dequant(Wq)^T
// CTA tile 64x64x64, 4 warps of 32x32, 128 threads, occupancy 3 (12 warps/SM).
// X tiles via cp.async from the pre-converted tile image; W dequantized in
// registers (I2F + FFMA(q,s,-z*s) + CVT). Double-buffered smem, one
// __syncthreads per K iter. A-fragments register-double-buffered across ks.
// Pair-permuted stride-72 rows -> conflict-free LDS.64 fragment reads.
// Linear blockIdx.x over (n-tile, split) pairs: the first n_hi n-tiles have
// split+1 K-splits, the rest split. blockIdx.z selects weight set.
// ---------------------------------------------------------------------------
__global__ __launch_bounds__(128, 3) void gemm_w4(
    const uint32_t* __restrict__ Xt,   // tile image, tile-major
    const int* __restrict__ qA, const float* __restrict__ scA, const float* __restrict__ zrA,
    float* __restrict__ opA,
    const int* __restrict__ qB, const float* __restrict__ scB, const float* __restrict__ zrB,
    float* __restrict__ opB,
    int Kdim, int ng, int Ntot, int split, int n_hi)
{
    const int* q; const float* sc; const float* zr; float* outp;
    if (blockIdx.z == 0) { q = qA; sc = scA; zr = zrA; outp = opA; }
    else                 { q = qB; sc = scB; zr = zrB; outp = opB; }

    extern __shared__ uint32_t smem[];
    uint32_t* sX = smem;                   // [2][64*72]
    uint32_t* sW = smem + 2 * TILE_WORDS;  // [2][64*72]
    const uint32_t sXu = (uint32_t)__cvta_generic_to_shared(sX);

    const int tid  = threadIdx.x;
    const int warp = tid >> 5;
    const int lane = tid & 31;
    const int qg   = lane >> 2;
    const int qt   = lane & 3;
    const int m0w  = (warp & 1) * 32;
    const int n0w  = (warp >> 1) * 32;

    // linear bid -> (n-tile, split index s, split count c_n)
    const int bx = blockIdx.x;
    const int hi_total = n_hi * (split + 1);
    int n_t, s, c_n;
    if (bx < hi_total) { n_t = bx / (split + 1); s = bx % (split + 1); c_n = split + 1; }
    else { const int b2 = bx - hi_total; n_t = n_hi + b2 / split; s = b2 % split; c_n = split; }
    const int n0 = n_t * 64;

    // uneven split-K by k-tile index (64-tile boundaries are group-aligned)
    const int T    = Kdim >> 6;
    const int t_lo = (T * s) / c_n;
    const int t_hi = (T * (s + 1)) / c_n;
    const int NT   = t_hi - t_lo;
    const int kbeg = t_lo << 6;

    const int ln  = tid >> 2;              // W loader row 0..31 (+32)
    const int lkb = (tid & 3) * 16;        // W loader k-base {0,16,32,48}

    const long wr0 = (long)(n0 + ln) * Kdim;
    const long wr1 = (long)(n0 + ln + 32) * Kdim;

    float acc[2][4][4];
#pragma unroll
    for (int mi = 0; mi < 2; ++mi)
#pragma unroll
        for (int j = 0; j < 4; ++j)
#pragma unroll
            for (int i = 0; i < 4; ++i) acc[mi][j][i] = 0.f;

    int4  wq[8];
    float s0, zs0, s1, zs1;   // zs = -z*s (per row-tile)

    auto load_w = [&](int k) {
        const int gk = kbeg + k * 64;
        const int gi = gk >> 7;
        s0 = sc[(n0 + ln) * ng + gi];
        zs0 = -zr[(n0 + ln) * ng + gi] * s0;
        s1 = sc[(n0 + ln + 32) * ng + gi];
        zs1 = -zr[(n0 + ln + 32) * ng + gi] * s1;
        const int4* p0 = (const int4*)(q + wr0 + gk + lkb);
        wq[0] = p0[0]; wq[1] = p0[1]; wq[2] = p0[2]; wq[3] = p0[3];
        const int4* p1 = (const int4*)(q + wr1 + gk + lkb);
        wq[4] = p1[0]; wq[5] = p1[1]; wq[6] = p1[2]; wq[7] = p1[3];
    };

    auto dq1 = [&](int v, float sv, float zs) -> uint32_t {
        return f2tf32(fmaf((float)v, sv, zs));
    };
    auto put_w = [&](uint32_t* dst, const int4& A, const int4& B, float sv, float zs) {
        ((uint4*)dst)[0] = make_uint4(dq1(A.x, sv, zs), dq1(B.x, sv, zs),
                                      dq1(A.y, sv, zs), dq1(B.y, sv, zs));
        ((uint4*)dst)[1] = make_uint4(dq1(A.z, sv, zs), dq1(B.z, sv, zs),
                                      dq1(A.w, sv, zs), dq1(B.w, sv, zs));
    };

    auto stage_w = [&](int buf) {
        uint32_t* d0 = &sW[buf + ln * 72 + lkb];
        put_w(d0,     wq[0], wq[1], s0, zs0);
        put_w(d0 + 8, wq[2], wq[3], s0, zs0);
        uint32_t* d1 = &sW[buf + (ln + 32) * 72 + lkb];
        put_w(d1,     wq[4], wq[5], s1, zs1);
        put_w(d1 + 8, wq[6], wq[7], s1, zs1);
    };

    // cp.async one X tile image (1152 x 16B chunks) into buffer
    auto fetch_x = [&](int k, int buf_bytes) {
        const char* src = (const char*)(Xt + (long)(t_lo + k) * TILE_WORDS);
#pragma unroll
        for (int j = 0; j < 9; ++j) {
            const int off = (j * 128 + tid) * 16;
            cp_async16(sXu + buf_bytes + off, src + off);
        }
        cp_commit();
    };

    // ---- prologue: X(0)+W(0) -> buf0, W(1) -> regs ----
    fetch_x(0, 0);
    load_w(0);
    stage_w(0);
    if (NT > 1) load_w(1);
    cp_wait0();
    __syncthreads();

    for (int k = 0; k < NT; ++k) {
        const int cur = (k & 1) * TILE_WORDS;
        const int nxt = ((k + 1) & 1) * TILE_WORDS;

        if (k + 1 < NT) {
            fetch_x(k + 1, nxt * 4);   // into buffer retired at last barrier
            stage_w(nxt);              // overlaps this iter's MMA
        }
        if (k + 2 < NT) load_w(k + 2); // LDG 2 iters ahead

        // ---- MMA with A-fragment register double-buffering across ks ----
        uint2 fa[2][4];
        {
            const int kk0 = 2 * qt;
            fa[0][0] = *(const uint2*)&sX[cur + (m0w + qg)      * 72 + kk0];
            fa[0][1] = *(const uint2*)&sX[cur + (m0w + qg + 8)  * 72 + kk0];
            fa[0][2] = *(const uint2*)&sX[cur + (m0w + qg + 16) * 72 + kk0];
            fa[0][3] = *(const uint2*)&sX[cur + (m0w + qg + 24) * 72 + kk0];
        }
#pragma unroll
        for (int ks = 0; ks < 8; ++ks) {
            const int kk = ks * 8 + 2 * qt;
            const int pc = ks & 1, pn = pc ^ 1;
            if (ks < 7) {
                const int kk1 = kk + 8;
                fa[pn][0] = *(const uint2*)&sX[cur + (m0w + qg)      * 72 + kk1];
                fa[pn][1] = *(const uint2*)&sX[cur + (m0w + qg + 8)  * 72 + kk1];
                fa[pn][2] = *(const uint2*)&sX[cur + (m0w + qg + 16) * 72 + kk1];
                fa[pn][3] = *(const uint2*)&sX[cur + (m0w + qg + 24) * 72 + kk1];
            }
#pragma unroll
            for (int j = 0; j < 4; ++j) {
                uint2 bb = *(const uint2*)&sW[cur + (n0w + j * 8 + qg) * 72 + kk];
                mma_tf32(acc[0][j], fa[pc][0].x, fa[pc][1].x, fa[pc][0].y, fa[pc][1].y, bb.x, bb.y);
                mma_tf32(acc[1][j], fa[pc][2].x, fa[pc][3].x, fa[pc][2].y, fa[pc][3].y, bb.x, bb.y);
            }
        }
        cp_wait0();       // X(k+1) landed (had the whole MMA block to fly)
        __syncthreads();  // publishes X(k+1)+W(k+1); retires reads of cur
    }

    float* ob = outp + (long)s * (B_DIM * (long)Ntot);
#pragma unroll
    for (int mi = 0; mi < 2; ++mi)
#pragma unroll
        for (int j = 0; j < 4; ++j) {
            const int row = m0w + mi * 16 + qg;
            const int col = n0 + n0w + j * 8 + qt * 2;
            *(float2*)&ob[(long)row * Ntot + col] =
                make_float2(acc[mi][j][0], acc[mi][j][1]);
            *(float2*)&ob[(long)(row + 8) * Ntot + col] =
                make_float2(acc[mi][j][2], acc[mi][j][3]);
        }
}

// ---------------------------------------------------------------------------
extern "C" void kernel_launch(void* const* d_in, const int* in_sizes, int n_in,
                              void* d_out, int out_size) {
    (void)in_sizes; (void)n_in; (void)out_size;
    const float* x  = (const float*)d_in[0];
    const int*   gq = (const int*)d_in[1];
    const float* gs = (const float*)d_in[2];
    const float* gz = (const float*)d_in[3];
    const int*   uq = (const int*)d_in[4];
    const float* us = (const float*)d_in[5];
    const float* uz = (const float*)d_in[6];
    const int*   dq = (const int*)d_in[7];
    const float* ds = (const float*)d_in[8];
    const float* dz = (const float*)d_in[9];
    float* out = (float*)d_out;

    // Unconditional (no static guards); idempotent and capture-safe.
    cudaFuncSetAttribute(gemm_w4, cudaFuncAttributeMaxDynamicSharedMemorySize, SMEM_BYTES);

    uint32_t* xt; cudaGetSymbolAddress((void**)&xt, g_xt);
    uint32_t* ht; cudaGetSymbolAddress((void**)&ht, g_ht);
    float* pg; cudaGetSymbolAddress((void**)&pg, g_pg);
    float* pu; cudaGetSymbolAddress((void**)&pu, g_pu);
    float* pd; cudaGetSymbolAddress((void**)&pd, g_pd);

    xcvt_kernel<<<dim3(H_DIM / 256, B_DIM), 256>>>(x);

    // gate + up: linear grid 172*7 = 1204 per matrix, z = 2 matrices
    // = 2408 CTAs = 5.4 waves at occ 3 (444 slots), 12 warps/SM.
    gemm_w4<<<dim3((I_DIM / 64) * GU_SPLIT, 1, 2), 128, SMEM_BYTES>>>(
        xt, gq, gs, gz, pg, uq, us, uz, pu,
        H_DIM, H_DIM / QGROUP, I_DIM, GU_SPLIT, 0);

    silu_kernel<<<dim3(I_DIM / 256, B_DIM), 256>>>();

    // down: 60 n-tiles x 7 splits + 4 n-tiles x 6 splits = 444 CTAs
    // = exactly one occ-3 wave (148 SMs x 3), no serialized tail.
    gemm_w4<<<dim3(DN_NHI * (DN_SPLIT + 1) + (H_DIM / 64 - DN_NHI) * DN_SPLIT, 1, 1),
              128, SMEM_BYTES>>>(
        ht, dq, ds, dz, pd, dq, ds, dz, pd,
        I_DIM, I_DIM / QGROUP, H_DIM, DN_SPLIT, DN_NHI);

    add_kernel<<<(B_DIM * H_DIM) / 512, 512>>>(out);
}